// round 8
// baseline (speedup 1.0000x reference)
#include <cuda_runtime.h>
#include <cuda_bf16.h>
#include <cstdint>

#define NU 100000          // users
#define NM 20000           // movies
#define NE 1000000         // edges per direction
#define NLOOP 20000        // self loops (min(NU,NM))
#define ET (NE + NLOOP)
#define HD 64

// ---------------- scratch (static device globals) ---------------------------
__device__ int   g_cntm[NM];
__device__ int   g_offm[NM + 1];
__device__ int   g_curm[NM];
__device__ int   g_csrm[ET];                  // src indices, movie-dst-grouped
__device__ float g_su[NU];                    // user segment sums of exp
__device__ float g_accu[(size_t)NU * HD];
__device__ float g_xlu[(size_t)NU * HD];   // user  src-proj (xl of u2m)
__device__ float g_xru[(size_t)NU * HD];   // user  dst-proj (xr of m2u)
__device__ float g_xlm[(size_t)NM * HD];   // movie src-proj (xl of m2u)
__device__ float g_xrm[(size_t)NM * HD];   // movie dst-proj (xr of u2m)
__device__ float g_xu[(size_t)NU * HD];    // layer-0 user output
__device__ float g_xm[(size_t)NM * HD];    // layer-0 movie output

// ---------------- movie CSR build -------------------------------------------
__global__ void zero_k(int* __restrict__ p, int n)
{
    int i = blockIdx.x * blockDim.x + threadIdx.x;
    if (i < n) p[i] = 0;
}

__global__ void histm_k(const int* __restrict__ edst, int* __restrict__ cnt)
{
    int e = blockIdx.x * blockDim.x + threadIdx.x;
    if (e >= ET) return;
    int d = (e < NE) ? edst[e] : e - NE;
    atomicAdd(&cnt[d], 1);
}

__global__ void scanm_k(const int* __restrict__ cnt, int* __restrict__ off,
                        int* __restrict__ cur)
{
    __shared__ int part[1024];
    int t = threadIdx.x;
    const int n = NM;
    int chunk = (n + 1023) >> 10;
    int b = t * chunk;
    int e = min(b + chunk, n);
    int s = 0;
    for (int i = b; i < e; i++) s += cnt[i];
    part[t] = s;
    __syncthreads();
    for (int o = 1; o < 1024; o <<= 1) {
        int v = (t >= o) ? part[t - o] : 0;
        __syncthreads();
        part[t] += v;
        __syncthreads();
    }
    int run = (t == 0) ? 0 : part[t - 1];
    for (int i = b; i < e; i++) {
        off[i] = run; cur[i] = run;
        run += cnt[i];
    }
    if (t == 1023) off[n] = part[1023];
}

__global__ void reorderm_k(const int* __restrict__ esrc, const int* __restrict__ edst,
                           int* __restrict__ cur, int* __restrict__ csr)
{
    int e = blockIdx.x * blockDim.x + threadIdx.x;
    if (e >= ET) return;
    int s, d;
    if (e < NE) { s = esrc[e]; d = edst[e]; } else { s = e - NE; d = s; }
    int pos = atomicAdd(&cur[d], 1);
    csr[pos] = s;
}

// ---------------- dual-side, dual-output GEMM --------------------------------
__global__ void gemm2_dual_k(const float* __restrict__ Xu, const float* __restrict__ Xm,
                             const float* __restrict__ W1u, const float* __restrict__ B1u,
                             const float* __restrict__ W2u, const float* __restrict__ B2u,
                             const float* __restrict__ W1m, const float* __restrict__ B1m,
                             const float* __restrict__ W2m, const float* __restrict__ B2m,
                             float* __restrict__ Y1u, float* __restrict__ Y2u,
                             float* __restrict__ Y1m, float* __restrict__ Y2m,
                             int GU)
{
    __shared__ float Xs[64][65];
    __shared__ float Ws1[64][64];
    __shared__ float Ws2[64][64];
    int tid = threadIdx.x;               // 256 threads
    int bid = blockIdx.x;

    const float *X, *W1, *B1, *W2, *B2;
    float *Y1, *Y2;
    int N;
    if (bid < GU) {
        X = Xu; W1 = W1u; B1 = B1u; W2 = W2u; B2 = B2u;
        Y1 = Y1u; Y2 = Y2u; N = NU;
    } else {
        bid -= GU;
        X = Xm; W1 = W1m; B1 = B1m; W2 = W2m; B2 = B2m;
        Y1 = Y1m; Y2 = Y2m; N = NM;
    }
    int row0 = bid * 64;

#pragma unroll
    for (int i = 0; i < 4; i++) {
        ((float4*)Ws1)[tid + i * 256] = ((const float4*)W1)[tid + i * 256];
        ((float4*)Ws2)[tid + i * 256] = ((const float4*)W2)[tid + i * 256];
    }
#pragma unroll
    for (int i = 0; i < 4; i++) {
        int idx = tid + i * 256;
        int r = idx >> 4, c4 = idx & 15;
        float4 v = make_float4(0.f, 0.f, 0.f, 0.f);
        if (row0 + r < N) v = ((const float4*)X)[(size_t)(row0 + r) * 16 + c4];
        Xs[r][c4 * 4 + 0] = v.x; Xs[r][c4 * 4 + 1] = v.y;
        Xs[r][c4 * 4 + 2] = v.z; Xs[r][c4 * 4 + 3] = v.w;
    }
    __syncthreads();

    int ty = tid >> 4, tx = tid & 15;
    float a1[4][4], a2[4][4];
#pragma unroll
    for (int i = 0; i < 4; i++)
#pragma unroll
        for (int j = 0; j < 4; j++) { a1[i][j] = 0.f; a2[i][j] = 0.f; }

#pragma unroll
    for (int k = 0; k < 64; k++) {
        float4 w1 = ((const float4*)Ws1)[k * 16 + tx];
        float4 w2 = ((const float4*)Ws2)[k * 16 + tx];
        float x0 = Xs[ty * 4 + 0][k];
        float x1 = Xs[ty * 4 + 1][k];
        float x2 = Xs[ty * 4 + 2][k];
        float x3 = Xs[ty * 4 + 3][k];
        a1[0][0] += x0*w1.x; a1[0][1] += x0*w1.y; a1[0][2] += x0*w1.z; a1[0][3] += x0*w1.w;
        a1[1][0] += x1*w1.x; a1[1][1] += x1*w1.y; a1[1][2] += x1*w1.z; a1[1][3] += x1*w1.w;
        a1[2][0] += x2*w1.x; a1[2][1] += x2*w1.y; a1[2][2] += x2*w1.z; a1[2][3] += x2*w1.w;
        a1[3][0] += x3*w1.x; a1[3][1] += x3*w1.y; a1[3][2] += x3*w1.z; a1[3][3] += x3*w1.w;
        a2[0][0] += x0*w2.x; a2[0][1] += x0*w2.y; a2[0][2] += x0*w2.z; a2[0][3] += x0*w2.w;
        a2[1][0] += x1*w2.x; a2[1][1] += x1*w2.y; a2[1][2] += x1*w2.z; a2[1][3] += x1*w2.w;
        a2[2][0] += x2*w2.x; a2[2][1] += x2*w2.y; a2[2][2] += x2*w2.z; a2[2][3] += x2*w2.w;
        a2[3][0] += x3*w2.x; a2[3][1] += x3*w2.y; a2[3][2] += x3*w2.z; a2[3][3] += x3*w2.w;
    }

    float4 b1 = ((const float4*)B1)[tx];
    float4 b2 = ((const float4*)B2)[tx];
#pragma unroll
    for (int i = 0; i < 4; i++) {
        int r = row0 + ty * 4 + i;
        if (r < N) {
            float4 o1, o2;
            o1.x = a1[i][0] + b1.x; o1.y = a1[i][1] + b1.y;
            o1.z = a1[i][2] + b1.z; o1.w = a1[i][3] + b1.w;
            o2.x = a2[i][0] + b2.x; o2.y = a2[i][1] + b2.y;
            o2.z = a2[i][2] + b2.z; o2.w = a2[i][3] + b2.w;
            ((float4*)Y1)[(size_t)r * 16 + tx] = o1;
            ((float4*)Y2)[(size_t)r * 16 + tx] = o2;
        }
    }
}

// ---------------- init user accumulator + user segment sums ------------------
__global__ void initu_k(float* __restrict__ su_, float* __restrict__ accu)
{
    int i = blockIdx.x * blockDim.x + threadIdx.x;
    const int N4 = NU * (HD / 4);
    if (i < N4) ((float4*)accu)[i] = make_float4(0.f, 0.f, 0.f, 0.f);
    if (i < NU) su_[i] = 0.f;
}

// ---------------- merged conv -----------------------------------------------
// blocks [0,NM): block-per-movie (u2m dst side), smem accumulate, write output
// blocks [NM,NM+CB): m2u scatter (R2 shape), red.v4 into accu + su atomics
__global__ void conv_merged_k(const int* __restrict__ offm, const int* __restrict__ csrm,
                              const int* __restrict__ em,
                              const float* __restrict__ xlu, const float* __restrict__ xrm,
                              const float* __restrict__ xlm, const float* __restrict__ xru,
                              const float* __restrict__ att0, const float* __restrict__ bias0,
                              const float* __restrict__ att1,
                              float* __restrict__ outm,
                              float* __restrict__ su_, float* __restrict__ accu)
{
    __shared__ float s_acc[16][64];
    __shared__ float s_sum[16];

    if (blockIdx.x < NM) {
        // ----- block-per-movie: out[d] = selu(bias + Σex·xl / Σex) -----------
        int d   = blockIdx.x;
        int tid = threadIdx.x;           // 256
        int gid = tid >> 4;              // 16 groups of 16 lanes
        int l16 = tid & 15;

        int beg = offm[d], end = offm[d + 1];
        int deg = end - beg;
        int iters = (deg + 15) >> 4;     // BLOCK-UNIFORM trip count (no shuffle divergence)

        float4 xr4 = ((const float4*)xrm)[(size_t)d * 16 + l16];
        float4 w4  = ((const float4*)att0)[l16];

        float4 acc = make_float4(0.f, 0.f, 0.f, 0.f);
        float  sum = 0.f;

        for (int it = 0; it < iters; it++) {
            int idx = beg + it * 16 + gid;
            bool v = idx < end;
            int s = csrm[v ? idx : beg];
            float4 a = ((const float4*)xlu)[(size_t)s * 16 + l16];
            float vx = a.x + xr4.x; vx = vx > 0.f ? vx : 0.2f * vx;
            float vy = a.y + xr4.y; vy = vy > 0.f ? vy : 0.2f * vy;
            float vz = a.z + xr4.z; vz = vz > 0.f ? vz : 0.2f * vz;
            float vw = a.w + xr4.w; vw = vw > 0.f ? vw : 0.2f * vw;
            float p = vx * w4.x + vy * w4.y + vz * w4.z + vw * w4.w;
#pragma unroll
            for (int o = 8; o > 0; o >>= 1) p += __shfl_xor_sync(0xffffffffu, p, o);
            float ex = v ? __expf(p) : 0.f;
            sum   += ex;
            acc.x += ex * a.x; acc.y += ex * a.y;
            acc.z += ex * a.z; acc.w += ex * a.w;
        }

        s_acc[gid][l16 * 4 + 0] = acc.x;
        s_acc[gid][l16 * 4 + 1] = acc.y;
        s_acc[gid][l16 * 4 + 2] = acc.z;
        s_acc[gid][l16 * 4 + 3] = acc.w;
        if (l16 == 0) s_sum[gid] = sum;
        __syncthreads();

        if (tid < 64) {
            float a = 0.f, tot = 0.f;
#pragma unroll
            for (int g2 = 0; g2 < 16; g2++) { a += s_acc[g2][tid]; tot += s_sum[g2]; }
            float x = a / (tot + 1e-16f) + bias0[tid];
            const float SCALE = 1.0507009873554805f;
            const float SA    = 1.7580993408473766f;
            outm[(size_t)d * HD + tid] = x > 0.f ? SCALE * x : SA * (__expf(x) - 1.f);
        }
    } else {
        // ----- m2u scatter: one 16-lane group per edge -----------------------
        int t = (blockIdx.x - NM) * blockDim.x + threadIdx.x;
        int g = t >> 4;
        if (g >= ET) return;
        int lane = t & 15;
        int s, d;
        if (g < NE) { s = em[g]; d = em[NE + g]; } else { s = g - NE; d = s; }

        float4 a = ((const float4*)xlm)[(size_t)s * 16 + lane];
        float4 b = ((const float4*)xru)[(size_t)d * 16 + lane];
        float4 w = ((const float4*)att1)[lane];

        float vx = a.x + b.x; vx = vx > 0.f ? vx : 0.2f * vx;
        float vy = a.y + b.y; vy = vy > 0.f ? vy : 0.2f * vy;
        float vz = a.z + b.z; vz = vz > 0.f ? vz : 0.2f * vz;
        float vw = a.w + b.w; vw = vw > 0.f ? vw : 0.2f * vw;
        float p = vx * w.x + vy * w.y + vz * w.z + vw * w.w;
#pragma unroll
        for (int o = 8; o > 0; o >>= 1) p += __shfl_xor_sync(0xffffffffu, p, o);
        float ex = __expf(p);

        if (lane == 0) atomicAdd(&su_[d], ex);

        a.x *= ex; a.y *= ex; a.z *= ex; a.w *= ex;
        float* pp = accu + (size_t)d * HD + lane * 4;
        asm volatile("red.global.add.v4.f32 [%0], {%1,%2,%3,%4};"
                     :: "l"(pp), "f"(a.x), "f"(a.y), "f"(a.z), "f"(a.w) : "memory");
    }
}

// ---------------- finalize users: /segsum, +bias, SELU -----------------------
__global__ void finalizeu_k(const float* __restrict__ accu, const float* __restrict__ su_,
                            const float* __restrict__ bias, float* __restrict__ out)
{
    int i = blockIdx.x * blockDim.x + threadIdx.x;
    if (i >= NU * HD) return;
    float inv = 1.f / (su_[i >> 6] + 1e-16f);
    float x = accu[i] * inv + bias[i & 63];
    const float SCALE = 1.0507009873554805f;
    const float SA    = 1.7580993408473766f;
    out[i] = x > 0.f ? SCALE * x : SA * (__expf(x) - 1.f);
}

// ---------------- host ------------------------------------------------------
extern "C" void kernel_launch(void* const* d_in, const int* in_sizes, int n_in,
                              void* d_out, int out_size)
{
    const float* x_user  = (const float*)d_in[0];
    const float* x_movie = (const float*)d_in[1];
    const int*   e_u2m   = (const int*)d_in[2];
    const int*   e_m2u   = (const int*)d_in[3];
    const float* Wl      = (const float*)d_in[4];
    const float* bl      = (const float*)d_in[5];
    const float* Wr      = (const float*)d_in[6];
    const float* br      = (const float*)d_in[7];
    const float* att     = (const float*)d_in[8];
    const float* bias    = (const float*)d_in[9];
    float* out = (float*)d_out;

    int *cntm, *offm, *curm, *csrm;
    float *su, *accu, *xlu, *xru, *xlm, *xrm, *xu, *xm;
    cudaGetSymbolAddress((void**)&cntm, g_cntm);
    cudaGetSymbolAddress((void**)&offm, g_offm);
    cudaGetSymbolAddress((void**)&curm, g_curm);
    cudaGetSymbolAddress((void**)&csrm, g_csrm);
    cudaGetSymbolAddress((void**)&su,   g_su);
    cudaGetSymbolAddress((void**)&accu, g_accu);
    cudaGetSymbolAddress((void**)&xlu,  g_xlu);
    cudaGetSymbolAddress((void**)&xru,  g_xru);
    cudaGetSymbolAddress((void**)&xlm,  g_xlm);
    cudaGetSymbolAddress((void**)&xrm,  g_xrm);
    cudaGetSymbolAddress((void**)&xu,   g_xu);
    cudaGetSymbolAddress((void**)&xm,   g_xm);

    const int EB = (ET + 255) / 256;
    const int GU = (NU + 63) / 64;
    const int GM = (NM + 63) / 64;
    const int CB = ((long)ET * 16 + 255) / 256;   // scatter blocks
    const int IB = (NU * (HD / 4) + 255) / 256;
    const int FB = (NU * HD + 255) / 256;

    // ---- movie-side CSR (built once, reused by both layers) ----------------
    zero_k<<<(NM + 255) / 256, 256>>>(cntm, NM);
    histm_k<<<EB, 256>>>(e_u2m + NE, cntm);
    scanm_k<<<1, 1024>>>(cntm, offm, curm);
    reorderm_k<<<EB, 256>>>(e_u2m, e_u2m + NE, curm, csrm);

    const float* cu = x_user;
    const float* cm = x_movie;

    for (int l = 0; l < 2; l++) {
        int p0 = l * 2 + 0;   // user -> movie
        int p1 = l * 2 + 1;   // movie -> user

        gemm2_dual_k<<<GU + GM, 256>>>(cu, cm,
            Wl + (size_t)p0 * 4096, bl + (size_t)p0 * 64,
            Wr + (size_t)p1 * 4096, br + (size_t)p1 * 64,
            Wl + (size_t)p1 * 4096, bl + (size_t)p1 * 64,
            Wr + (size_t)p0 * 4096, br + (size_t)p0 * 64,
            xlu, xru, xlm, xrm, GU);

        initu_k<<<IB, 256>>>(su, accu);

        float* om = (l == 1) ? (out + (size_t)NU * HD) : xm;
        float* ou = (l == 1) ? out : xu;

        conv_merged_k<<<NM + CB, 256>>>(offm, csrm, e_m2u,
            xlu, xrm, xlm, xru,
            att + (size_t)p0 * 64, bias + (size_t)p0 * 64,
            att + (size_t)p1 * 64,
            om, su, accu);

        finalizeu_k<<<FB, 256>>>(accu, su, bias + (size_t)p1 * 64, ou);

        cu = xu;
        cm = xm;
    }
}

// round 9
// speedup vs baseline: 1.1066x; 1.1066x over previous
#include <cuda_runtime.h>
#include <cuda_bf16.h>
#include <cstdint>

#define NU 100000          // users
#define NM 20000           // movies
#define NE 1000000         // edges per direction
#define NLOOP 20000        // self loops (min(NU,NM))
#define ET (NE + NLOOP)
#define HD 64

// ---------------- scratch (static device globals; zero at module load) ------
__device__ float g_sm[NM],   g_su[NU];        // segment sums of exp
__device__ float g_accm[(size_t)NM * HD];     // zeroed at end of each launch
__device__ float g_accu[(size_t)NU * HD];
__device__ float g_xlu[(size_t)NU * HD];   // user  src-proj (xl of u2m)
__device__ float g_xru[(size_t)NU * HD];   // user  dst-proj (xr of m2u)
__device__ float g_xlm[(size_t)NM * HD];   // movie src-proj (xl of m2u)
__device__ float g_xrm[(size_t)NM * HD];   // movie dst-proj (xr of u2m)
__device__ float g_xu[(size_t)NU * HD];    // layer-0 user output
__device__ float g_xm[(size_t)NM * HD];    // layer-0 movie output

// ---------------- dual-side, dual-output GEMM + fused segsum zero ------------
// blocks [0,GU): user rows; blocks [GU,..): movie rows.
// Also zeroes sm/su (consumed later this layer by conv) via grid-stride.
__global__ void gemm2_dual_k(const float* __restrict__ Xu, const float* __restrict__ Xm,
                             const float* __restrict__ W1u, const float* __restrict__ B1u,
                             const float* __restrict__ W2u, const float* __restrict__ B2u,
                             const float* __restrict__ W1m, const float* __restrict__ B1m,
                             const float* __restrict__ W2m, const float* __restrict__ B2m,
                             float* __restrict__ Y1u, float* __restrict__ Y2u,
                             float* __restrict__ Y1m, float* __restrict__ Y2m,
                             float* __restrict__ sm_, float* __restrict__ su_,
                             int GU)
{
    // fused zeroing of segment-sum buffers (safe: prior finalize already read them)
    for (int z = blockIdx.x * blockDim.x + threadIdx.x; z < NM + NU;
         z += gridDim.x * blockDim.x) {
        if (z < NM) sm_[z] = 0.f; else su_[z - NM] = 0.f;
    }

    __shared__ float Xs[64][65];
    __shared__ float Ws1[64][64];
    __shared__ float Ws2[64][64];
    int tid = threadIdx.x;               // 256 threads
    int bid = blockIdx.x;

    const float *X, *W1, *B1, *W2, *B2;
    float *Y1, *Y2;
    int N;
    if (bid < GU) {
        X = Xu; W1 = W1u; B1 = B1u; W2 = W2u; B2 = B2u;
        Y1 = Y1u; Y2 = Y2u; N = NU;
    } else {
        bid -= GU;
        X = Xm; W1 = W1m; B1 = B1m; W2 = W2m; B2 = B2m;
        Y1 = Y1m; Y2 = Y2m; N = NM;
    }
    int row0 = bid * 64;

#pragma unroll
    for (int i = 0; i < 4; i++) {
        ((float4*)Ws1)[tid + i * 256] = ((const float4*)W1)[tid + i * 256];
        ((float4*)Ws2)[tid + i * 256] = ((const float4*)W2)[tid + i * 256];
    }
#pragma unroll
    for (int i = 0; i < 4; i++) {
        int idx = tid + i * 256;
        int r = idx >> 4, c4 = idx & 15;
        float4 v = make_float4(0.f, 0.f, 0.f, 0.f);
        if (row0 + r < N) v = ((const float4*)X)[(size_t)(row0 + r) * 16 + c4];
        Xs[r][c4 * 4 + 0] = v.x; Xs[r][c4 * 4 + 1] = v.y;
        Xs[r][c4 * 4 + 2] = v.z; Xs[r][c4 * 4 + 3] = v.w;
    }
    __syncthreads();

    int ty = tid >> 4, tx = tid & 15;
    float a1[4][4], a2[4][4];
#pragma unroll
    for (int i = 0; i < 4; i++)
#pragma unroll
        for (int j = 0; j < 4; j++) { a1[i][j] = 0.f; a2[i][j] = 0.f; }

#pragma unroll
    for (int k = 0; k < 64; k++) {
        float4 w1 = ((const float4*)Ws1)[k * 16 + tx];
        float4 w2 = ((const float4*)Ws2)[k * 16 + tx];
        float x0 = Xs[ty * 4 + 0][k];
        float x1 = Xs[ty * 4 + 1][k];
        float x2 = Xs[ty * 4 + 2][k];
        float x3 = Xs[ty * 4 + 3][k];
        a1[0][0] += x0*w1.x; a1[0][1] += x0*w1.y; a1[0][2] += x0*w1.z; a1[0][3] += x0*w1.w;
        a1[1][0] += x1*w1.x; a1[1][1] += x1*w1.y; a1[1][2] += x1*w1.z; a1[1][3] += x1*w1.w;
        a1[2][0] += x2*w1.x; a1[2][1] += x2*w1.y; a1[2][2] += x2*w1.z; a1[2][3] += x2*w1.w;
        a1[3][0] += x3*w1.x; a1[3][1] += x3*w1.y; a1[3][2] += x3*w1.z; a1[3][3] += x3*w1.w;
        a2[0][0] += x0*w2.x; a2[0][1] += x0*w2.y; a2[0][2] += x0*w2.z; a2[0][3] += x0*w2.w;
        a2[1][0] += x1*w2.x; a2[1][1] += x1*w2.y; a2[1][2] += x1*w2.z; a2[1][3] += x1*w2.w;
        a2[2][0] += x2*w2.x; a2[2][1] += x2*w2.y; a2[2][2] += x2*w2.z; a2[2][3] += x2*w2.w;
        a2[3][0] += x3*w2.x; a2[3][1] += x3*w2.y; a2[3][2] += x3*w2.z; a2[3][3] += x3*w2.w;
    }

    float4 b1 = ((const float4*)B1)[tx];
    float4 b2 = ((const float4*)B2)[tx];
#pragma unroll
    for (int i = 0; i < 4; i++) {
        int r = row0 + ty * 4 + i;
        if (r < N) {
            float4 o1, o2;
            o1.x = a1[i][0] + b1.x; o1.y = a1[i][1] + b1.y;
            o1.z = a1[i][2] + b1.z; o1.w = a1[i][3] + b1.w;
            o2.x = a2[i][0] + b2.x; o2.y = a2[i][1] + b2.y;
            o2.z = a2[i][2] + b2.z; o2.w = a2[i][3] + b2.w;
            ((float4*)Y1)[(size_t)r * 16 + tx] = o1;
            ((float4*)Y2)[(size_t)r * 16 + tx] = o2;
        }
    }
}

// ---------------- fused edge pass, both directions in one launch -------------
__global__ void conv_dual_k(const int* __restrict__ eu, const int* __restrict__ em,
                            const float* __restrict__ xlu, const float* __restrict__ xrm,
                            const float* __restrict__ xlm, const float* __restrict__ xru,
                            const float* __restrict__ att0, const float* __restrict__ att1,
                            float* __restrict__ sm_, float* __restrict__ su_,
                            float* __restrict__ accm, float* __restrict__ accu,
                            int CB)
{
    const int *esrc, *edst;
    const float *xl, *xr, *att;
    float *sbuf, *acc;
    int bid = blockIdx.x;
    if (bid < CB) {
        esrc = eu; edst = eu + NE; xl = xlu; xr = xrm; att = att0;
        sbuf = sm_; acc = accm;
    } else {
        bid -= CB;
        esrc = em; edst = em + NE; xl = xlm; xr = xru; att = att1;
        sbuf = su_; acc = accu;
    }

    int t = bid * blockDim.x + threadIdx.x;
    int g = t >> 4;
    if (g >= ET) return;
    int lane = t & 15;
    int s, d;
    if (g < NE) { s = esrc[g]; d = edst[g]; } else { s = g - NE; d = s; }

    float4 a = ((const float4*)xl)[(size_t)s * 16 + lane];
    float4 b = ((const float4*)xr)[(size_t)d * 16 + lane];
    float4 w = ((const float4*)att)[lane];

    float vx = a.x + b.x; vx = vx > 0.f ? vx : 0.2f * vx;
    float vy = a.y + b.y; vy = vy > 0.f ? vy : 0.2f * vy;
    float vz = a.z + b.z; vz = vz > 0.f ? vz : 0.2f * vz;
    float vw = a.w + b.w; vw = vw > 0.f ? vw : 0.2f * vw;
    float p = vx * w.x + vy * w.y + vz * w.z + vw * w.w;
#pragma unroll
    for (int o = 8; o > 0; o >>= 1) p += __shfl_xor_sync(0xffffffffu, p, o);
    float ex = __expf(p);

    if (lane == 0) atomicAdd(&sbuf[d], ex);

    a.x *= ex; a.y *= ex; a.z *= ex; a.w *= ex;
    float* pp = acc + (size_t)d * HD + lane * 4;
    asm volatile("red.global.add.v4.f32 [%0], {%1,%2,%3,%4};"
                 :: "l"(pp), "f"(a.x), "f"(a.y), "f"(a.z), "f"(a.w) : "memory");
}

// ---------------- finalize (float4) + re-zero acc ----------------------------
// One thread = one float4. Reads acc, writes selu((acc/s)+bias) to out,
// then stores zeros back to acc (ready for next layer / next launch).
__global__ void finalize2_k(float* __restrict__ accm, const float* __restrict__ sm_,
                            const float* __restrict__ bias0, float* __restrict__ outm,
                            float* __restrict__ accu, const float* __restrict__ su_,
                            const float* __restrict__ bias1, float* __restrict__ outu)
{
    int i = blockIdx.x * blockDim.x + threadIdx.x;   // float4 index
    const int NM4 = NM * (HD / 4);
    const int NT4 = (NM + NU) * (HD / 4);
    if (i >= NT4) return;

    float* acc; const float* sbuf; const float* bias; float* out; int j;
    if (i < NM4) { acc = accm; sbuf = sm_; bias = bias0; out = outm; j = i; }
    else         { acc = accu; sbuf = su_; bias = bias1; out = outu; j = i - NM4; }

    int row = j >> 4;
    int c4  = j & 15;
    float inv = 1.f / (sbuf[row] + 1e-16f);
    float4 a = ((const float4*)acc)[j];
    float4 b = ((const float4*)bias)[c4];

    const float SCALE = 1.0507009873554805f;
    const float SA    = 1.7580993408473766f;   // scale * alpha
    float4 o;
    o.x = a.x * inv + b.x; o.x = o.x > 0.f ? SCALE * o.x : SA * (__expf(o.x) - 1.f);
    o.y = a.y * inv + b.y; o.y = o.y > 0.f ? SCALE * o.y : SA * (__expf(o.y) - 1.f);
    o.z = a.z * inv + b.z; o.z = o.z > 0.f ? SCALE * o.z : SA * (__expf(o.z) - 1.f);
    o.w = a.w * inv + b.w; o.w = o.w > 0.f ? SCALE * o.w : SA * (__expf(o.w) - 1.f);

    ((float4*)out)[j] = o;
    ((float4*)acc)[j] = make_float4(0.f, 0.f, 0.f, 0.f);   // re-zero for next use
}

// ---------------- host ------------------------------------------------------
extern "C" void kernel_launch(void* const* d_in, const int* in_sizes, int n_in,
                              void* d_out, int out_size)
{
    const float* x_user  = (const float*)d_in[0];
    const float* x_movie = (const float*)d_in[1];
    const int*   e_u2m   = (const int*)d_in[2];
    const int*   e_m2u   = (const int*)d_in[3];
    const float* Wl      = (const float*)d_in[4];
    const float* bl      = (const float*)d_in[5];
    const float* Wr      = (const float*)d_in[6];
    const float* br      = (const float*)d_in[7];
    const float* att     = (const float*)d_in[8];
    const float* bias    = (const float*)d_in[9];
    float* out = (float*)d_out;

    float *sm, *su, *accm, *accu, *xlu, *xru, *xlm, *xrm, *xu, *xm;
    cudaGetSymbolAddress((void**)&sm,   g_sm);
    cudaGetSymbolAddress((void**)&su,   g_su);
    cudaGetSymbolAddress((void**)&accm, g_accm);
    cudaGetSymbolAddress((void**)&accu, g_accu);
    cudaGetSymbolAddress((void**)&xlu,  g_xlu);
    cudaGetSymbolAddress((void**)&xru,  g_xru);
    cudaGetSymbolAddress((void**)&xlm,  g_xlm);
    cudaGetSymbolAddress((void**)&xrm,  g_xrm);
    cudaGetSymbolAddress((void**)&xu,   g_xu);
    cudaGetSymbolAddress((void**)&xm,   g_xm);

    const int GU  = (NU + 63) / 64;               // 1563 user gemm blocks
    const int GM  = (NM + 63) / 64;               // 313 movie gemm blocks
    const int CB  = ((long)ET * 16 + 255) / 256;  // 63750 conv blocks per direction
    const int FB4 = ((NM + NU) * (HD / 4) + 255) / 256;

    const float* cu = x_user;
    const float* cm = x_movie;

    for (int l = 0; l < 2; l++) {
        int p0 = l * 2 + 0;   // user -> movie
        int p1 = l * 2 + 1;   // movie -> user

        gemm2_dual_k<<<GU + GM, 256>>>(cu, cm,
            Wl + (size_t)p0 * 4096, bl + (size_t)p0 * 64,
            Wr + (size_t)p1 * 4096, br + (size_t)p1 * 64,
            Wl + (size_t)p1 * 4096, bl + (size_t)p1 * 64,
            Wr + (size_t)p0 * 4096, br + (size_t)p0 * 64,
            xlu, xru, xlm, xrm, sm, su, GU);

        conv_dual_k<<<2 * CB, 256>>>(e_u2m, e_m2u, xlu, xrm, xlm, xru,
            att + (size_t)p0 * 64, att + (size_t)p1 * 64,
            sm, su, accm, accu, CB);

        float* om = (l == 1) ? (out + (size_t)NU * HD) : xm;
        float* ou = (l == 1) ? out : xu;
        finalize2_k<<<FB4, 256>>>(accm, sm, bias + (size_t)p0 * 64, om,
                                  accu, su, bias + (size_t)p1 * 64, ou);

        cu = xu;
        cm = xm;
    }
}

// round 10
// speedup vs baseline: 1.1670x; 1.0546x over previous
#include <cuda_runtime.h>
#include <cuda_bf16.h>
#include <cstdint>

#define NU 100000          // users
#define NM 20000           // movies
#define NE 1000000         // edges per direction
#define NLOOP 20000        // self loops (min(NU,NM))
#define ET (NE + NLOOP)
#define HD 64

// ---------------- scratch (static device globals; zero at module load) ------
__device__ float g_sm[NM],   g_su[NU];        // segment sums of exp
__device__ float g_accm[(size_t)NM * HD];     // re-zeroed by finalize each layer
__device__ float g_accu[(size_t)NU * HD];
__device__ float g_xlu[(size_t)NU * HD];   // user  src-proj (xl of u2m)
__device__ float g_xru[(size_t)NU * HD];   // user  dst-proj (xr of m2u)
__device__ float g_xlm[(size_t)NM * HD];   // movie src-proj (xl of m2u)
__device__ float g_xrm[(size_t)NM * HD];   // movie dst-proj (xr of u2m)
__device__ float g_xu[(size_t)NU * HD];    // layer-0 user output
__device__ float g_xm[(size_t)NM * HD];    // layer-0 movie output

// ---------------- tf32 helpers ----------------------------------------------
__device__ __forceinline__ void split_tf32(float x, uint32_t& hi, uint32_t& lo)
{
    uint32_t h;
    asm("cvt.rna.tf32.f32 %0, %1;" : "=r"(h) : "f"(x));
    float r = x - __uint_as_float(h);
    uint32_t l;
    asm("cvt.rna.tf32.f32 %0, %1;" : "=r"(l) : "f"(r));
    hi = h; lo = l;
}

__device__ __forceinline__ void mma_tf32(float c[4],
                                         uint32_t a0, uint32_t a1, uint32_t a2, uint32_t a3,
                                         uint32_t b0, uint32_t b1)
{
    asm volatile("mma.sync.aligned.m16n8k8.row.col.f32.tf32.tf32.f32 "
                 "{%0,%1,%2,%3}, {%4,%5,%6,%7}, {%8,%9}, {%0,%1,%2,%3};"
                 : "+f"(c[0]), "+f"(c[1]), "+f"(c[2]), "+f"(c[3])
                 : "r"(a0), "r"(a1), "r"(a2), "r"(a3), "r"(b0), "r"(b1));
}

// ---------------- tensor-core dual-side, dual-output GEMM --------------------
// blocks [0,GU): user rows; [GU,GU+GM): movie rows. Per block: 64 rows x both
// projections (Y1 = X@W1+B1, Y2 = X@W2+B2) via 3xTF32 mma (fp32 accuracy).
// Also zeroes the segment-sum buffers (consumed later this layer by conv).
__global__ void gemm2_tc_k(const float* __restrict__ Xu, const float* __restrict__ Xm,
                           const float* __restrict__ W1u, const float* __restrict__ B1u,
                           const float* __restrict__ W2u, const float* __restrict__ B2u,
                           const float* __restrict__ W1m, const float* __restrict__ B1m,
                           const float* __restrict__ W2m, const float* __restrict__ B2m,
                           float* __restrict__ Y1u, float* __restrict__ Y2u,
                           float* __restrict__ Y1m, float* __restrict__ Y2m,
                           float* __restrict__ sm_, float* __restrict__ su_,
                           int GU)
{
    // fused zeroing of segment-sum buffers (prior finalize already read them)
    for (int z = blockIdx.x * blockDim.x + threadIdx.x; z < NM + NU;
         z += gridDim.x * blockDim.x) {
        if (z < NM) sm_[z] = 0.f; else su_[z - NM] = 0.f;
    }

    __shared__ float Xs[64][68];     // stride 68: A-frag LDS is bank-conflict-free

    int tid = threadIdx.x;           // 256 threads
    int bid = blockIdx.x;

    const float *X, *W1, *B1, *W2, *B2;
    float *Y1, *Y2;
    int N;
    if (bid < GU) {
        X = Xu; W1 = W1u; B1 = B1u; W2 = W2u; B2 = B2u;
        Y1 = Y1u; Y2 = Y2u; N = NU;
    } else {
        bid -= GU;
        X = Xm; W1 = W1m; B1 = B1m; W2 = W2m; B2 = B2m;
        Y1 = Y1m; Y2 = Y2m; N = NM;
    }
    int rowblk = bid * 64;

    // fill Xs[64][64 used of 68]
#pragma unroll
    for (int i = 0; i < 4; i++) {
        int idx = tid + i * 256;     // float4 index over [64][16]
        int r = idx >> 4, c4 = idx & 15;
        float4 v = make_float4(0.f, 0.f, 0.f, 0.f);
        if (rowblk + r < N) v = ((const float4*)X)[(size_t)(rowblk + r) * 16 + c4];
        *(float4*)&Xs[r][c4 * 4] = v;
    }
    __syncthreads();

    int wid  = tid >> 5;
    int lane = tid & 31;
    int warp_m = wid & 3;            // row group of 16
    int warp_n = wid >> 2;           // 0 -> (W1,B1,Y1), 1 -> (W2,B2,Y2)
    const float* W  = warp_n ? W2 : W1;
    const float* Bv = warp_n ? B2 : B1;
    float*       Y  = warp_n ? Y2 : Y1;

    int row0 = warp_m * 16;
    int qid = lane >> 2;             // t/4 : 0..7
    int rid = lane & 3;              // t%4 : 0..3

    float c[8][4];
#pragma unroll
    for (int nt = 0; nt < 8; nt++)
#pragma unroll
        for (int j = 0; j < 4; j++) c[nt][j] = 0.f;

#pragma unroll
    for (int k0 = 0; k0 < 64; k0 += 8) {
        // A fragment (m16 x k8), rows row0+qid / +8, cols k0+rid / +4
        float fa0 = Xs[row0 + qid    ][k0 + rid    ];
        float fa1 = Xs[row0 + qid + 8][k0 + rid    ];
        float fa2 = Xs[row0 + qid    ][k0 + rid + 4];
        float fa3 = Xs[row0 + qid + 8][k0 + rid + 4];
        uint32_t ah0, al0, ah1, al1, ah2, al2, ah3, al3;
        split_tf32(fa0, ah0, al0);
        split_tf32(fa1, ah1, al1);
        split_tf32(fa2, ah2, al2);
        split_tf32(fa3, ah3, al3);

#pragma unroll
        for (int nt = 0; nt < 8; nt++) {
            // B fragment (k8 x n8): b0 = W[k0+rid][n], b1 = W[k0+rid+4][n], n = nt*8+qid
            int n = nt * 8 + qid;
            float fb0 = __ldg(&W[(k0 + rid    ) * 64 + n]);
            float fb1 = __ldg(&W[(k0 + rid + 4) * 64 + n]);
            uint32_t bh0, bl0, bh1, bl1;
            split_tf32(fb0, bh0, bl0);
            split_tf32(fb1, bh1, bl1);

            mma_tf32(c[nt], ah0, ah1, ah2, ah3, bh0, bh1);   // hi*hi
            mma_tf32(c[nt], ah0, ah1, ah2, ah3, bl0, bl1);   // hi*lo
            mma_tf32(c[nt], al0, al1, al2, al3, bh0, bh1);   // lo*hi
        }
    }

    // epilogue: + bias, store float2 pairs
    int r0 = rowblk + row0 + qid;
    int r1 = r0 + 8;
#pragma unroll
    for (int nt = 0; nt < 8; nt++) {
        int cb = nt * 8 + rid * 2;
        float2 bv = *(const float2*)&Bv[cb];
        if (r0 < N) {
            float2 o; o.x = c[nt][0] + bv.x; o.y = c[nt][1] + bv.y;
            *(float2*)&Y[(size_t)r0 * 64 + cb] = o;
        }
        if (r1 < N) {
            float2 o; o.x = c[nt][2] + bv.x; o.y = c[nt][3] + bv.y;
            *(float2*)&Y[(size_t)r1 * 64 + cb] = o;
        }
    }
}

// ---------------- fused edge pass, both directions in one launch -------------
__global__ void conv_dual_k(const int* __restrict__ eu, const int* __restrict__ em,
                            const float* __restrict__ xlu, const float* __restrict__ xrm,
                            const float* __restrict__ xlm, const float* __restrict__ xru,
                            const float* __restrict__ att0, const float* __restrict__ att1,
                            float* __restrict__ sm_, float* __restrict__ su_,
                            float* __restrict__ accm, float* __restrict__ accu,
                            int CB)
{
    const int *esrc, *edst;
    const float *xl, *xr, *att;
    float *sbuf, *acc;
    int bid = blockIdx.x;
    if (bid < CB) {
        esrc = eu; edst = eu + NE; xl = xlu; xr = xrm; att = att0;
        sbuf = sm_; acc = accm;
    } else {
        bid -= CB;
        esrc = em; edst = em + NE; xl = xlm; xr = xru; att = att1;
        sbuf = su_; acc = accu;
    }

    int t = bid * blockDim.x + threadIdx.x;
    int g = t >> 4;
    if (g >= ET) return;
    int lane = t & 15;
    int s, d;
    if (g < NE) { s = esrc[g]; d = edst[g]; } else { s = g - NE; d = s; }

    float4 a = ((const float4*)xl)[(size_t)s * 16 + lane];
    float4 b = ((const float4*)xr)[(size_t)d * 16 + lane];
    float4 w = ((const float4*)att)[lane];

    float vx = a.x + b.x; vx = vx > 0.f ? vx : 0.2f * vx;
    float vy = a.y + b.y; vy = vy > 0.f ? vy : 0.2f * vy;
    float vz = a.z + b.z; vz = vz > 0.f ? vz : 0.2f * vz;
    float vw = a.w + b.w; vw = vw > 0.f ? vw : 0.2f * vw;
    float p = vx * w.x + vy * w.y + vz * w.z + vw * w.w;
#pragma unroll
    for (int o = 8; o > 0; o >>= 1) p += __shfl_xor_sync(0xffffffffu, p, o);
    float ex = __expf(p);

    if (lane == 0) atomicAdd(&sbuf[d], ex);

    a.x *= ex; a.y *= ex; a.z *= ex; a.w *= ex;
    float* pp = acc + (size_t)d * HD + lane * 4;
    asm volatile("red.global.add.v4.f32 [%0], {%1,%2,%3,%4};"
                 :: "l"(pp), "f"(a.x), "f"(a.y), "f"(a.z), "f"(a.w) : "memory");
}

// ---------------- finalize (float4) + re-zero acc ----------------------------
__global__ void finalize2_k(float* __restrict__ accm, const float* __restrict__ sm_,
                            const float* __restrict__ bias0, float* __restrict__ outm,
                            float* __restrict__ accu, const float* __restrict__ su_,
                            const float* __restrict__ bias1, float* __restrict__ outu)
{
    int i = blockIdx.x * blockDim.x + threadIdx.x;   // float4 index
    const int NM4 = NM * (HD / 4);
    const int NT4 = (NM + NU) * (HD / 4);
    if (i >= NT4) return;

    float* acc; const float* sbuf; const float* bias; float* out; int j;
    if (i < NM4) { acc = accm; sbuf = sm_; bias = bias0; out = outm; j = i; }
    else         { acc = accu; sbuf = su_; bias = bias1; out = outu; j = i - NM4; }

    int row = j >> 4;
    int c4  = j & 15;
    float inv = 1.f / (sbuf[row] + 1e-16f);
    float4 a = ((const float4*)acc)[j];
    float4 b = ((const float4*)bias)[c4];

    const float SCALE = 1.0507009873554805f;
    const float SA    = 1.7580993408473766f;   // scale * alpha
    float4 o;
    o.x = a.x * inv + b.x; o.x = o.x > 0.f ? SCALE * o.x : SA * (__expf(o.x) - 1.f);
    o.y = a.y * inv + b.y; o.y = o.y > 0.f ? SCALE * o.y : SA * (__expf(o.y) - 1.f);
    o.z = a.z * inv + b.z; o.z = o.z > 0.f ? SCALE * o.z : SA * (__expf(o.z) - 1.f);
    o.w = a.w * inv + b.w; o.w = o.w > 0.f ? SCALE * o.w : SA * (__expf(o.w) - 1.f);

    ((float4*)out)[j] = o;
    ((float4*)acc)[j] = make_float4(0.f, 0.f, 0.f, 0.f);   // re-zero for next use
}

// ---------------- host ------------------------------------------------------
extern "C" void kernel_launch(void* const* d_in, const int* in_sizes, int n_in,
                              void* d_out, int out_size)
{
    const float* x_user  = (const float*)d_in[0];
    const float* x_movie = (const float*)d_in[1];
    const int*   e_u2m   = (const int*)d_in[2];
    const int*   e_m2u   = (const int*)d_in[3];
    const float* Wl      = (const float*)d_in[4];
    const float* bl      = (const float*)d_in[5];
    const float* Wr      = (const float*)d_in[6];
    const float* br      = (const float*)d_in[7];
    const float* att     = (const float*)d_in[8];
    const float* bias    = (const float*)d_in[9];
    float* out = (float*)d_out;

    float *sm, *su, *accm, *accu, *xlu, *xru, *xlm, *xrm, *xu, *xm;
    cudaGetSymbolAddress((void**)&sm,   g_sm);
    cudaGetSymbolAddress((void**)&su,   g_su);
    cudaGetSymbolAddress((void**)&accm, g_accm);
    cudaGetSymbolAddress((void**)&accu, g_accu);
    cudaGetSymbolAddress((void**)&xlu,  g_xlu);
    cudaGetSymbolAddress((void**)&xru,  g_xru);
    cudaGetSymbolAddress((void**)&xlm,  g_xlm);
    cudaGetSymbolAddress((void**)&xrm,  g_xrm);
    cudaGetSymbolAddress((void**)&xu,   g_xu);
    cudaGetSymbolAddress((void**)&xm,   g_xm);

    const int GU  = (NU + 63) / 64;               // 1563 user gemm blocks
    const int GM  = (NM + 63) / 64;               // 313 movie gemm blocks
    const int CB  = ((long)ET * 16 + 255) / 256;  // 63750 conv blocks per direction
    const int FB4 = ((NM + NU) * (HD / 4) + 255) / 256;

    const float* cu = x_user;
    const float* cm = x_movie;

    for (int l = 0; l < 2; l++) {
        int p0 = l * 2 + 0;   // user -> movie
        int p1 = l * 2 + 1;   // movie -> user

        gemm2_tc_k<<<GU + GM, 256>>>(cu, cm,
            Wl + (size_t)p0 * 4096, bl + (size_t)p0 * 64,
            Wr + (size_t)p1 * 4096, br + (size_t)p1 * 64,
            Wl + (size_t)p1 * 4096, bl + (size_t)p1 * 64,
            Wr + (size_t)p0 * 4096, br + (size_t)p0 * 64,
            xlu, xru, xlm, xrm, sm, su, GU);

        conv_dual_k<<<2 * CB, 256>>>(e_u2m, e_m2u, xlu, xrm, xlm, xru,
            att + (size_t)p0 * 64, att + (size_t)p1 * 64,
            sm, su, accm, accu, CB);

        float* om = (l == 1) ? (out + (size_t)NU * HD) : xm;
        float* ou = (l == 1) ? out : xu;
        finalize2_k<<<FB4, 256>>>(accm, sm, bias + (size_t)p0 * 64, om,
                                  accu, su, bias + (size_t)p1 * 64, ou);

        cu = xu;
        cm = xm;
    }
}